// round 10
// baseline (speedup 1.0000x reference)
#include <cuda_runtime.h>
#include <cuda_fp16.h>
#include <cstdint>

// Problem constants (C=32,H=32,W=32,KS=3, B=32)
constexpr int NDIM = 32 * 32 * 32 + 1;   // 32769
constexpr int KDIM = 32 * 3 * 3;         // 288
constexpr int BDIM = 32;

constexpr int QCNT    = KDIM / 32;       // 9
constexpr int CLUSTER = 8;               // portable cluster size
constexpr int THREADS = 1024;            // 32 warps, 1 CTA/SM
constexpr int NCTAS   = 144;             // 18 clusters, all-resident on 148+ SMs
constexpr int ROWS_PER_CTA_ITER = 32;    // one row per warp per iteration
constexpr int NITER   = (NDIM + ROWS_PER_CTA_ITER - 1) / ROWS_PER_CTA_ITER; // 1025

constexpr unsigned T_DS      = 8192;     // cols < T_DS served from cluster DSMEM
constexpr int      SHARD_ROWS = T_DS / CLUSTER;        // 1024 rows per CTA
constexpr int      SHARD_BYTES = SHARD_ROWS * 64;      // 64 KB

// x transposed to [N, B] in fp16 (64 B rows).
__device__ __half g_xT[(size_t)NDIM * BDIM];

// ---------------------------------------------------------------------------
// Kernel 1: transpose + fp16-convert x [B, N] -> x_T [N, B].
// ---------------------------------------------------------------------------
__global__ __launch_bounds__(1024) void transpose_kernel(const float* __restrict__ x)
{
    __shared__ float tile[32][33];
    const int n0 = blockIdx.x * 32;
    const int tx = threadIdx.x;
    const int ty = threadIdx.y;

    const int n_load = n0 + tx;
    if (n_load < NDIM)
        tile[ty][tx] = x[(size_t)ty * NDIM + n_load];
    __syncthreads();

    const int n_store = n0 + ty;
    if (n_store < NDIM)
        g_xT[(size_t)n_store * BDIM + tx] = __float2half(tile[tx][ty]);
}

// ---------------------------------------------------------------------------
// Gather helper: cols < T_DS come from cluster DSMEM (rank = col>>10, row
// col&1023 in that CTA's 64KB shard); others from global x_T via L2.
// ---------------------------------------------------------------------------
__device__ __forceinline__ uint4 gather_one(unsigned c,
                                            const char* __restrict__ xb_global,
                                            uint32_t shard_u32, int quad)
{
    uint4 h;
    if (c < T_DS) {
        uint32_t laddr = shard_u32 + ((c & (SHARD_ROWS - 1)) << 6) + (quad << 4);
        uint32_t rank  = c >> 10;
        uint32_t raddr;
        asm("mapa.shared::cluster.u32 %0, %1, %2;" : "=r"(raddr) : "r"(laddr), "r"(rank));
        asm volatile("ld.shared::cluster.v4.b32 {%0,%1,%2,%3}, [%4];"
                     : "=r"(h.x), "=r"(h.y), "=r"(h.z), "=r"(h.w) : "r"(raddr));
    } else {
        h = __ldg((const uint4*)(xb_global + ((size_t)c << 6)));
    }
    return h;
}

__device__ __forceinline__ void fma8(float* acc, float v, uint4 h)
{
    float2 f0 = __half22float2(*(const __half2*)&h.x);
    float2 f1 = __half22float2(*(const __half2*)&h.y);
    float2 f2 = __half22float2(*(const __half2*)&h.z);
    float2 f3 = __half22float2(*(const __half2*)&h.w);
    acc[0] = fmaf(v, f0.x, acc[0]); acc[1] = fmaf(v, f0.y, acc[1]);
    acc[2] = fmaf(v, f1.x, acc[2]); acc[3] = fmaf(v, f1.y, acc[3]);
    acc[4] = fmaf(v, f2.x, acc[4]); acc[5] = fmaf(v, f2.y, acc[5]);
    acc[6] = fmaf(v, f3.x, acc[6]); acc[7] = fmaf(v, f3.y, acc[7]);
}

// ---------------------------------------------------------------------------
// Kernel 2: clustered gather-dot. 1024 threads (32 warps), cluster of 8 CTAs.
// Each CTA caches 1024 x_T rows (64KB dyn smem); cluster collectively owns
// cols [0, 8192) -> those gathers ride the DSMEM fabric instead of the
// LTS-cap-saturated L2 path. Warp w handles row base+w; 32 consecutive rows
// per CTA iteration give a fully coalesced block epilogue.
// ---------------------------------------------------------------------------
__global__ __launch_bounds__(THREADS, 1) __cluster_dims__(CLUSTER, 1, 1)
void gather_cluster_kernel(const float* __restrict__ vals,
                           const int*   __restrict__ cols,
                           float*       __restrict__ out)
{
    extern __shared__ __align__(16) char s_shard[];          // 64 KB dynamic
    __shared__ float s_acc[2][ROWS_PER_CTA_ITER][33];        // double-buffered

    const int tid  = threadIdx.x;
    const int w    = tid >> 5;
    const int lane = tid & 31;
    const int g    = lane >> 2;   // group 0..7 (k within 32-k chunk)
    const int quad = lane & 3;    // 16B slice -> b = quad*8 .. quad*8+7

    uint32_t rank;
    asm("mov.u32 %0, %%cluster_ctarank;" : "=r"(rank));
    uint32_t shard_u32;
    asm("{ .reg .u64 t; cvta.to.shared.u64 t, %1; cvt.u32.u64 %0, t; }"
        : "=r"(shard_u32) : "l"(s_shard));

    // Load my shard: rows [rank*1024, rank*1024+1024) of g_xT (64 KB).
    {
        const uint4* src = (const uint4*)((const char*)g_xT + (size_t)rank * SHARD_BYTES);
        uint4* dst = (uint4*)s_shard;
        #pragma unroll
        for (int i = 0; i < SHARD_BYTES / 16 / THREADS; ++i)
            dst[i * THREADS + tid] = src[i * THREADS + tid];
    }
    // Publish shards cluster-wide before any remote reads.
    asm volatile("barrier.cluster.arrive.aligned;" ::: "memory");
    asm volatile("barrier.cluster.wait.aligned;"   ::: "memory");

    int buf = 0;
    for (int rb = blockIdx.x; rb < NITER; rb += NCTAS, buf ^= 1) {
        const int n = rb * ROWS_PER_CTA_ITER + w;

        float acc[8] = {0.f, 0.f, 0.f, 0.f, 0.f, 0.f, 0.f, 0.f};

        if (n < NDIM) {
            const int4*   cp = (const int4*)  (cols + (size_t)n * KDIM) + g;
            const float4* vp = (const float4*)(vals + (size_t)n * KDIM) + g;
            const char*   xb = (const char*)g_xT + quad * 16;

            int4   cc = __ldg(cp);
            float4 vv = __ldg(vp);

            #pragma unroll
            for (int q = 0; q < QCNT; ++q) {
                int4   c = cc;
                float4 v = vv;
                if (q + 1 < QCNT) {
                    cc = __ldg(cp + (q + 1) * 8);
                    vv = __ldg(vp + (q + 1) * 8);
                }
                // Pairwise gathers keep register pressure <= 64 at 1024 thr.
                uint4 h0 = gather_one((unsigned)c.x, xb, shard_u32, quad);
                uint4 h1 = gather_one((unsigned)c.y, xb, shard_u32, quad);
                fma8(acc, v.x, h0);
                fma8(acc, v.y, h1);
                h0 = gather_one((unsigned)c.z, xb, shard_u32, quad);
                h1 = gather_one((unsigned)c.w, xb, shard_u32, quad);
                fma8(acc, v.z, h0);
                fma8(acc, v.w, h1);
            }
        }

        // Butterfly-reduce over the 8 groups (lane bits [2:4]).
        #pragma unroll
        for (int s = 4; s < 32; s <<= 1) {
            #pragma unroll
            for (int j = 0; j < 8; ++j)
                acc[j] += __shfl_xor_sync(0xffffffffu, acc[j], s);
        }

        if (lane < 4) {
            #pragma unroll
            for (int j = 0; j < 8; ++j)
                s_acc[buf][w][lane * 8 + j] = acc[j];
        }
        __syncthreads();   // single barrier; buffers alternate per iteration

        // Coalesced epilogue: thread t -> b = t/32, j = t%32;
        // 32 consecutive n per b = one full 128B line.
        const int b  = tid >> 5;
        const int j  = tid & 31;
        const int nn = rb * ROWS_PER_CTA_ITER + j;
        if (nn < NDIM)
            out[(size_t)b * NDIM + nn] = s_acc[buf][j][b];
    }

    // No CTA may exit while peers can still read its shard.
    asm volatile("barrier.cluster.arrive.aligned;" ::: "memory");
    asm volatile("barrier.cluster.wait.aligned;"   ::: "memory");
}

// ---------------------------------------------------------------------------
// kernel_launch: inputs per metadata order: x_affine (f32), vals (f32), cols (i32)
// ---------------------------------------------------------------------------
extern "C" void kernel_launch(void* const* d_in, const int* in_sizes, int n_in,
                              void* d_out, int out_size)
{
    const float* x    = (const float*)d_in[0];
    const float* vals = (const float*)d_in[1];
    const int*   cols = (const int*)  d_in[2];
    float*       out  = (float*)d_out;

    (void)in_sizes; (void)n_in; (void)out_size;

    static bool attr_set = false;
    if (!attr_set) {
        cudaFuncSetAttribute(gather_cluster_kernel,
                             cudaFuncAttributeMaxDynamicSharedMemorySize,
                             SHARD_BYTES);
        attr_set = true;
    }

    {
        dim3 block(32, 32);
        dim3 grid((NDIM + 31) / 32);
        transpose_kernel<<<grid, block>>>(x);
    }
    {
        // __cluster_dims__(8,1,1) is baked into the kernel; plain launch OK.
        gather_cluster_kernel<<<NCTAS, THREADS, SHARD_BYTES>>>(vals, cols, out);
    }
}

// round 11
// speedup vs baseline: 3.4228x; 3.4228x over previous
#include <cuda_runtime.h>
#include <cuda_fp16.h>
#include <cstdint>

// Problem constants (C=32,H=32,W=32,KS=3, B=32)
constexpr int NDIM = 32 * 32 * 32 + 1;   // 32769
constexpr int KDIM = 32 * 3 * 3;         // 288
constexpr int BDIM = 32;

constexpr int WARPS_PER_BLOCK = 8;
constexpr int NBLK = (NDIM + WARPS_PER_BLOCK - 1) / WARPS_PER_BLOCK;  // 4097
constexpr int GRID = 148 * 4;                                          // 592
constexpr int QCNT = KDIM / 32;                                        // 9

// x transposed to [N, B] in fp16: 64 B rows; one LDG.128 with 4-lane groups
// gathers EIGHT different rows per instruction.
__device__ __half g_xT[(size_t)NDIM * BDIM];

// ---------------------------------------------------------------------------
// Kernel 1: transpose + fp16-convert x [B, N] -> x_T [N, B].
// Signals PDL dependents as soon as this CTA's stores are issued.
// ---------------------------------------------------------------------------
__global__ __launch_bounds__(1024) void transpose_kernel(const float* __restrict__ x)
{
    __shared__ float tile[32][33];
    const int n0 = blockIdx.x * 32;
    const int tx = threadIdx.x;
    const int ty = threadIdx.y;

    const int n_load = n0 + tx;
    if (n_load < NDIM)
        tile[ty][tx] = x[(size_t)ty * NDIM + n_load];
    __syncthreads();

    const int n_store = n0 + ty;
    if (n_store < NDIM)
        g_xT[(size_t)n_store * BDIM + tx] = __float2half(tile[tx][ty]);

    // PDL: this CTA's contribution to x_T is done (stores issued; memory
    // consistency to the dependent grid is guaranteed by the PDL edge).
    asm volatile("griddepcontrol.launch_dependents;" ::: "memory");
}

// ---------------------------------------------------------------------------
// Kernel 2 (persistent, PDL secondary): warp handles row n; grid-stride.
// Feed: one int4 + one float4 per group per q (1 wf per 32 k's per array).
// Gather: 4 LDG.128 per group per q, each servicing 8 fp16 rows.
// The q=0 feed loads for the first row-block are issued BEFORE
// griddepcontrol.wait — they don't read x_T, so they overlap the transpose
// tail and hide the launch gap + feed latency.
// ---------------------------------------------------------------------------
__global__ __launch_bounds__(WARPS_PER_BLOCK * 32, 4)
void gather_dot_kernel(const float* __restrict__ vals,
                       const int*   __restrict__ cols,
                       float*       __restrict__ out)
{
    __shared__ float s_acc[2][WARPS_PER_BLOCK][33];   // double-buffered

    const int w    = threadIdx.x >> 5;
    const int lane = threadIdx.x & 31;
    const int g    = lane >> 2;   // group 0..7
    const int quad = lane & 3;    // 16B slice -> b = quad*8 .. quad*8+7

    // ---- PDL prologue: prefetch first row-block's q=0 feed (no x_T use) ----
    const int n_first = blockIdx.x * WARPS_PER_BLOCK + w;
    int4   c_pre = make_int4(0, 0, 0, 0);
    float4 v_pre = make_float4(0.f, 0.f, 0.f, 0.f);
    if (n_first < NDIM) {
        c_pre = __ldg((const int4*)  (cols + (size_t)n_first * KDIM) + g);
        v_pre = __ldg((const float4*)(vals + (size_t)n_first * KDIM) + g);
    }
    // Now require the primary grid (transpose) to be fully done before any
    // gather touches x_T.
    asm volatile("griddepcontrol.wait;" ::: "memory");

    int buf = 0;
    bool first = true;
    for (int rb = blockIdx.x; rb < NBLK; rb += GRID, buf ^= 1) {
        const int n = rb * WARPS_PER_BLOCK + w;

        float acc[8] = {0.f, 0.f, 0.f, 0.f, 0.f, 0.f, 0.f, 0.f};

        if (n < NDIM) {
            const int4*   cp = (const int4*)  (cols + (size_t)n * KDIM) + g;
            const float4* vp = (const float4*)(vals + (size_t)n * KDIM) + g;
            const char*   xb = (const char*)g_xT + quad * 16;

            int4   c;
            float4 v;
            if (first) { c = c_pre; v = v_pre; }
            else       { c = __ldg(cp); v = __ldg(vp); }

            #pragma unroll
            for (int q = 0; q < QCNT; ++q) {
                // 4 independent gathers for this q (the cap-bound stream)
                uint4 h0 = __ldg((const uint4*)(xb + ((size_t)(unsigned)c.x << 6)));
                uint4 h1 = __ldg((const uint4*)(xb + ((size_t)(unsigned)c.y << 6)));
                uint4 h2 = __ldg((const uint4*)(xb + ((size_t)(unsigned)c.z << 6)));
                uint4 h3 = __ldg((const uint4*)(xb + ((size_t)(unsigned)c.w << 6)));
                float4 vc = v;

                // prefetch feed for q+1 while the gathers are in flight
                if (q + 1 < QCNT) {
                    c = __ldg(cp + (q + 1) * 8);
                    v = __ldg(vp + (q + 1) * 8);
                }

                {
                    float2 f0 = __half22float2(*(const __half2*)&h0.x);
                    float2 f1 = __half22float2(*(const __half2*)&h0.y);
                    float2 f2 = __half22float2(*(const __half2*)&h0.z);
                    float2 f3 = __half22float2(*(const __half2*)&h0.w);
                    acc[0] = fmaf(vc.x, f0.x, acc[0]); acc[1] = fmaf(vc.x, f0.y, acc[1]);
                    acc[2] = fmaf(vc.x, f1.x, acc[2]); acc[3] = fmaf(vc.x, f1.y, acc[3]);
                    acc[4] = fmaf(vc.x, f2.x, acc[4]); acc[5] = fmaf(vc.x, f2.y, acc[5]);
                    acc[6] = fmaf(vc.x, f3.x, acc[6]); acc[7] = fmaf(vc.x, f3.y, acc[7]);
                }
                {
                    float2 f0 = __half22float2(*(const __half2*)&h1.x);
                    float2 f1 = __half22float2(*(const __half2*)&h1.y);
                    float2 f2 = __half22float2(*(const __half2*)&h1.z);
                    float2 f3 = __half22float2(*(const __half2*)&h1.w);
                    acc[0] = fmaf(vc.y, f0.x, acc[0]); acc[1] = fmaf(vc.y, f0.y, acc[1]);
                    acc[2] = fmaf(vc.y, f1.x, acc[2]); acc[3] = fmaf(vc.y, f1.y, acc[3]);
                    acc[4] = fmaf(vc.y, f2.x, acc[4]); acc[5] = fmaf(vc.y, f2.y, acc[5]);
                    acc[6] = fmaf(vc.y, f3.x, acc[6]); acc[7] = fmaf(vc.y, f3.y, acc[7]);
                }
                {
                    float2 f0 = __half22float2(*(const __half2*)&h2.x);
                    float2 f1 = __half22float2(*(const __half2*)&h2.y);
                    float2 f2 = __half22float2(*(const __half2*)&h2.z);
                    float2 f3 = __half22float2(*(const __half2*)&h2.w);
                    acc[0] = fmaf(vc.z, f0.x, acc[0]); acc[1] = fmaf(vc.z, f0.y, acc[1]);
                    acc[2] = fmaf(vc.z, f1.x, acc[2]); acc[3] = fmaf(vc.z, f1.y, acc[3]);
                    acc[4] = fmaf(vc.z, f2.x, acc[4]); acc[5] = fmaf(vc.z, f2.y, acc[5]);
                    acc[6] = fmaf(vc.z, f3.x, acc[6]); acc[7] = fmaf(vc.z, f3.y, acc[7]);
                }
                {
                    float2 f0 = __half22float2(*(const __half2*)&h3.x);
                    float2 f1 = __half22float2(*(const __half2*)&h3.y);
                    float2 f2 = __half22float2(*(const __half2*)&h3.z);
                    float2 f3 = __half22float2(*(const __half2*)&h3.w);
                    acc[0] = fmaf(vc.w, f0.x, acc[0]); acc[1] = fmaf(vc.w, f0.y, acc[1]);
                    acc[2] = fmaf(vc.w, f1.x, acc[2]); acc[3] = fmaf(vc.w, f1.y, acc[3]);
                    acc[4] = fmaf(vc.w, f2.x, acc[4]); acc[5] = fmaf(vc.w, f2.y, acc[5]);
                    acc[6] = fmaf(vc.w, f3.x, acc[6]); acc[7] = fmaf(vc.w, f3.y, acc[7]);
                }
            }
        }
        first = false;

        // Butterfly-reduce over the 8 groups (lane bits [2:4]).
        #pragma unroll
        for (int s = 4; s < 32; s <<= 1) {
            #pragma unroll
            for (int j = 0; j < 8; ++j)
                acc[j] += __shfl_xor_sync(0xffffffffu, acc[j], s);
        }

        if (lane < 4) {
            #pragma unroll
            for (int j = 0; j < 8; ++j)
                s_acc[buf][w][lane * 8 + j] = acc[j];
        }
        __syncthreads();   // single barrier; buffers alternate per iteration

        // Sector-coalesced store: thread t -> b = t/8, j = t%8.
        const int b  = threadIdx.x >> 3;
        const int j  = threadIdx.x & 7;
        const int nn = rb * WARPS_PER_BLOCK + j;
        if (nn < NDIM)
            out[(size_t)b * NDIM + nn] = s_acc[buf][j][b];
    }
}

// ---------------------------------------------------------------------------
// kernel_launch: inputs per metadata order: x_affine (f32), vals (f32), cols (i32)
// ---------------------------------------------------------------------------
extern "C" void kernel_launch(void* const* d_in, const int* in_sizes, int n_in,
                              void* d_out, int out_size)
{
    const float* x    = (const float*)d_in[0];
    const float* vals = (const float*)d_in[1];
    const int*   cols = (const int*)  d_in[2];
    float*       out  = (float*)d_out;

    (void)in_sizes; (void)n_in; (void)out_size;

    // Carveout = 10%: fits 4 resident blocks while maximizing L1D (per R8).
    static bool attr_set = false;
    if (!attr_set) {
        cudaFuncSetAttribute(gather_dot_kernel,
                             cudaFuncAttributePreferredSharedMemoryCarveout, 10);
        attr_set = true;
    }

    // Primary: transpose.
    {
        dim3 block(32, 32);
        dim3 grid((NDIM + 31) / 32);
        transpose_kernel<<<grid, block>>>(x);
    }

    // Secondary: gather-dot, launched as a PDL dependent so its prologue
    // (feed prefetch) overlaps the transpose tail.
    {
        cudaLaunchConfig_t cfg = {};
        cfg.gridDim  = dim3(GRID);
        cfg.blockDim = dim3(WARPS_PER_BLOCK * 32);
        cudaLaunchAttribute attrs[1];
        attrs[0].id = cudaLaunchAttributeProgrammaticStreamSerialization;
        attrs[0].val.programmaticStreamSerializationAllowed = 1;
        cfg.attrs    = attrs;
        cfg.numAttrs = 1;
        cudaLaunchKernelEx(&cfg, gather_dot_kernel, vals, cols, out);
    }
}

// round 12
// speedup vs baseline: 3.7508x; 1.0958x over previous
#include <cuda_runtime.h>
#include <cuda_fp16.h>
#include <cstdint>

// Problem constants (C=32,H=32,W=32,KS=3, B=32)
constexpr int NDIM = 32 * 32 * 32 + 1;   // 32769
constexpr int KDIM = 32 * 3 * 3;         // 288
constexpr int BDIM = 32;

constexpr int WARPS_PER_BLOCK = 8;
constexpr int NBLK = (NDIM + WARPS_PER_BLOCK - 1) / WARPS_PER_BLOCK;  // 4097
constexpr int QCNT = KDIM / 32;                                        // 9

// x transposed to [N, B] in fp16: 64 B rows; one LDG.128 with 4-lane groups
// gathers EIGHT different rows per instruction.
__device__ __half g_xT[(size_t)NDIM * BDIM];

// ---------------------------------------------------------------------------
// Kernel 1: transpose + fp16-convert x [B, N] -> x_T [N, B].
// ---------------------------------------------------------------------------
__global__ __launch_bounds__(1024) void transpose_kernel(const float* __restrict__ x)
{
    __shared__ float tile[32][33];
    const int n0 = blockIdx.x * 32;
    const int tx = threadIdx.x;
    const int ty = threadIdx.y;

    const int n_load = n0 + tx;
    if (n_load < NDIM)
        tile[ty][tx] = x[(size_t)ty * NDIM + n_load];
    __syncthreads();

    const int n_store = n0 + ty;
    if (n_store < NDIM)
        g_xT[(size_t)n_store * BDIM + tx] = __float2half(tile[tx][ty]);
}

// ---------------------------------------------------------------------------
// Kernel 2: one warp per output row n, one block per 8 rows (4097 blocks;
// hardware scheduler balances the tail better than static grid-striding).
//   g = lane>>2 : k within a 32-k chunk; quad = lane&3 : 16B slice of row.
// Feed: one int4 + one float4 per group per q -> 1 wavefront per 32 k's per
// array (8 groups span exactly one 128B line; rows are 1152B = 9 lines).
// Gather: 4 LDG.128 per group per q, each servicing 8 different fp16 rows.
// This stream runs at the LTS sector cap (~604MB of L2->SM traffic), which
// is the measured structural floor for this problem.
// ---------------------------------------------------------------------------
__global__ __launch_bounds__(WARPS_PER_BLOCK * 32, 4)
void gather_dot_kernel(const float* __restrict__ vals,
                       const int*   __restrict__ cols,
                       float*       __restrict__ out)
{
    __shared__ float s_acc[WARPS_PER_BLOCK][33];   // [n_off][b], padded

    const int w    = threadIdx.x >> 5;
    const int lane = threadIdx.x & 31;
    const int g    = lane >> 2;   // group 0..7
    const int quad = lane & 3;    // 16B slice -> b = quad*8 .. quad*8+7
    const int n    = blockIdx.x * WARPS_PER_BLOCK + w;

    float acc[8] = {0.f, 0.f, 0.f, 0.f, 0.f, 0.f, 0.f, 0.f};

    if (n < NDIM) {
        const int4*   cp = (const int4*)  (cols + (size_t)n * KDIM) + g;
        const float4* vp = (const float4*)(vals + (size_t)n * KDIM) + g;
        const char*   xb = (const char*)g_xT + quad * 16;

        int4   c = __ldg(cp);          // feed q=0 (1 wf across warp)
        float4 v = __ldg(vp);

        #pragma unroll
        for (int q = 0; q < QCNT; ++q) {
            // 4 independent gathers for this q (the cap-bound stream)
            uint4 h0 = __ldg((const uint4*)(xb + ((size_t)(unsigned)c.x << 6)));
            uint4 h1 = __ldg((const uint4*)(xb + ((size_t)(unsigned)c.y << 6)));
            uint4 h2 = __ldg((const uint4*)(xb + ((size_t)(unsigned)c.z << 6)));
            uint4 h3 = __ldg((const uint4*)(xb + ((size_t)(unsigned)c.w << 6)));
            float4 vc = v;

            // prefetch feed for q+1 while the gathers are in flight
            if (q + 1 < QCNT) {
                c = __ldg(cp + (q + 1) * 8);
                v = __ldg(vp + (q + 1) * 8);
            }

            {
                float2 f0 = __half22float2(*(const __half2*)&h0.x);
                float2 f1 = __half22float2(*(const __half2*)&h0.y);
                float2 f2 = __half22float2(*(const __half2*)&h0.z);
                float2 f3 = __half22float2(*(const __half2*)&h0.w);
                acc[0] = fmaf(vc.x, f0.x, acc[0]); acc[1] = fmaf(vc.x, f0.y, acc[1]);
                acc[2] = fmaf(vc.x, f1.x, acc[2]); acc[3] = fmaf(vc.x, f1.y, acc[3]);
                acc[4] = fmaf(vc.x, f2.x, acc[4]); acc[5] = fmaf(vc.x, f2.y, acc[5]);
                acc[6] = fmaf(vc.x, f3.x, acc[6]); acc[7] = fmaf(vc.x, f3.y, acc[7]);
            }
            {
                float2 f0 = __half22float2(*(const __half2*)&h1.x);
                float2 f1 = __half22float2(*(const __half2*)&h1.y);
                float2 f2 = __half22float2(*(const __half2*)&h1.z);
                float2 f3 = __half22float2(*(const __half2*)&h1.w);
                acc[0] = fmaf(vc.y, f0.x, acc[0]); acc[1] = fmaf(vc.y, f0.y, acc[1]);
                acc[2] = fmaf(vc.y, f1.x, acc[2]); acc[3] = fmaf(vc.y, f1.y, acc[3]);
                acc[4] = fmaf(vc.y, f2.x, acc[4]); acc[5] = fmaf(vc.y, f2.y, acc[5]);
                acc[6] = fmaf(vc.y, f3.x, acc[6]); acc[7] = fmaf(vc.y, f3.y, acc[7]);
            }
            {
                float2 f0 = __half22float2(*(const __half2*)&h2.x);
                float2 f1 = __half22float2(*(const __half2*)&h2.y);
                float2 f2 = __half22float2(*(const __half2*)&h2.z);
                float2 f3 = __half22float2(*(const __half2*)&h2.w);
                acc[0] = fmaf(vc.z, f0.x, acc[0]); acc[1] = fmaf(vc.z, f0.y, acc[1]);
                acc[2] = fmaf(vc.z, f1.x, acc[2]); acc[3] = fmaf(vc.z, f1.y, acc[3]);
                acc[4] = fmaf(vc.z, f2.x, acc[4]); acc[5] = fmaf(vc.z, f2.y, acc[5]);
                acc[6] = fmaf(vc.z, f3.x, acc[6]); acc[7] = fmaf(vc.z, f3.y, acc[7]);
            }
            {
                float2 f0 = __half22float2(*(const __half2*)&h3.x);
                float2 f1 = __half22float2(*(const __half2*)&h3.y);
                float2 f2 = __half22float2(*(const __half2*)&h3.z);
                float2 f3 = __half22float2(*(const __half2*)&h3.w);
                acc[0] = fmaf(vc.w, f0.x, acc[0]); acc[1] = fmaf(vc.w, f0.y, acc[1]);
                acc[2] = fmaf(vc.w, f1.x, acc[2]); acc[3] = fmaf(vc.w, f1.y, acc[3]);
                acc[4] = fmaf(vc.w, f2.x, acc[4]); acc[5] = fmaf(vc.w, f2.y, acc[5]);
                acc[6] = fmaf(vc.w, f3.x, acc[6]); acc[7] = fmaf(vc.w, f3.y, acc[7]);
            }
        }
    }

    // Butterfly-reduce over the 8 groups (lane bits [2:4]).
    #pragma unroll
    for (int s = 4; s < 32; s <<= 1) {
        #pragma unroll
        for (int j = 0; j < 8; ++j)
            acc[j] += __shfl_xor_sync(0xffffffffu, acc[j], s);
    }

    // Lanes 0..3 hold final sums for b = quad*8 + j.
    if (lane < 4) {
        #pragma unroll
        for (int j = 0; j < 8; ++j)
            s_acc[w][lane * 8 + j] = acc[j];
    }
    __syncthreads();

    // Sector-coalesced store: thread t -> b = t/8, j = t%8 (8 consecutive n).
    const int b  = threadIdx.x >> 3;
    const int j  = threadIdx.x & 7;
    const int nn = blockIdx.x * WARPS_PER_BLOCK + j;
    if (nn < NDIM)
        out[(size_t)b * NDIM + nn] = s_acc[j][b];
}

// ---------------------------------------------------------------------------
// kernel_launch: inputs per metadata order: x_affine (f32), vals (f32), cols (i32)
// ---------------------------------------------------------------------------
extern "C" void kernel_launch(void* const* d_in, const int* in_sizes, int n_in,
                              void* d_out, int out_size)
{
    const float* x    = (const float*)d_in[0];
    const float* vals = (const float*)d_in[1];
    const int*   cols = (const int*)  d_in[2];
    float*       out  = (float*)d_out;

    (void)in_sizes; (void)n_in; (void)out_size;

    {
        dim3 block(32, 32);
        dim3 grid((NDIM + 31) / 32);
        transpose_kernel<<<grid, block>>>(x);
    }
    {
        gather_dot_kernel<<<NBLK, WARPS_PER_BLOCK * 32>>>(vals, cols, out);
    }
}

// round 13
// speedup vs baseline: 3.8851x; 1.0358x over previous
#include <cuda_runtime.h>
#include <cuda_fp16.h>
#include <cstdint>

// Problem constants (C=32,H=32,W=32,KS=3, B=32)
constexpr int NDIM = 32 * 32 * 32 + 1;   // 32769
constexpr int KDIM = 32 * 3 * 3;         // 288
constexpr int BDIM = 32;

constexpr int WARPS_PER_BLOCK = 8;
constexpr int NBLK = (NDIM + WARPS_PER_BLOCK - 1) / WARPS_PER_BLOCK;  // 4097
constexpr int QCNT = KDIM / 32;                                        // 9

// x transposed to [N, B] in fp16: 64 B rows; one LDG.128 with 4-lane groups
// gathers EIGHT different rows per instruction.
__device__ __align__(16) __half g_xT[(size_t)NDIM * BDIM];

// ---------------------------------------------------------------------------
// Kernel 1: transpose + fp16-convert x [B, N] -> x_T [N, B].
// 64 n-rows per 256-thread block. Loads are scalar (NDIM odd -> rows are not
// 16B aligned) but fully coalesced along n. Stage in smem as tile[n][b] with
// a 40-half row stride (80B: 16B-aligned for LDS.128, bounded STS conflicts),
// then each thread stores ONE uint4 -> full 128B store lines to g_xT.
// ---------------------------------------------------------------------------
constexpr int TP_STRIDE = 40;   // halves per smem row (80 B, 16B-aligned)

__global__ __launch_bounds__(256) void transpose_kernel(const float* __restrict__ x)
{
    __shared__ __half tile[64][TP_STRIDE];

    const int n0 = blockIdx.x * 64;
    const int t  = threadIdx.x;

    // Load + convert: 64 n x 32 b = 2048 elements, 8 per thread.
    // idx -> b = idx/64, nl = idx%64: lanes hit consecutive n (coalesced).
    #pragma unroll
    for (int i = 0; i < 8; ++i) {
        const int idx = i * 256 + t;
        const int b   = idx >> 6;
        const int nl  = idx & 63;
        const int n   = n0 + nl;
        if (n < NDIM)
            tile[nl][b] = __float2half(x[(size_t)b * NDIM + n]);
    }
    __syncthreads();

    // Store: thread t -> row nl = t/4, quad = t%4; one 16B chunk (8 b's).
    // 8 threads per 64B row; 128B store lines fully packed.
    const int nl   = t >> 2;
    const int quad = t & 3;
    const int n    = n0 + nl;
    if (n < NDIM) {
        uint4 u = *(const uint4*)&tile[nl][quad * 8];   // LDS.128, 16B-aligned
        *(uint4*)((char*)g_xT + (size_t)n * 64 + quad * 16) = u;
    }
}

// ---------------------------------------------------------------------------
// Kernel 2 (unchanged from R12 best): one warp per output row n, 4097 blocks.
//   g = lane>>2 : k within a 32-k chunk; quad = lane&3 : 16B slice of row.
// Feed: one int4 + one float4 per group per q -> 1 wavefront per 32 k's per
// array. Gather: 4 LDG.128 per group per q, each servicing 8 fp16 rows.
// Runs at the LTS sector cap (~604MB L2->SM) = the structural floor.
// ---------------------------------------------------------------------------
__global__ __launch_bounds__(WARPS_PER_BLOCK * 32, 4)
void gather_dot_kernel(const float* __restrict__ vals,
                       const int*   __restrict__ cols,
                       float*       __restrict__ out)
{
    __shared__ float s_acc[WARPS_PER_BLOCK][33];   // [n_off][b], padded

    const int w    = threadIdx.x >> 5;
    const int lane = threadIdx.x & 31;
    const int g    = lane >> 2;   // group 0..7
    const int quad = lane & 3;    // 16B slice -> b = quad*8 .. quad*8+7
    const int n    = blockIdx.x * WARPS_PER_BLOCK + w;

    float acc[8] = {0.f, 0.f, 0.f, 0.f, 0.f, 0.f, 0.f, 0.f};

    if (n < NDIM) {
        const int4*   cp = (const int4*)  (cols + (size_t)n * KDIM) + g;
        const float4* vp = (const float4*)(vals + (size_t)n * KDIM) + g;
        const char*   xb = (const char*)g_xT + quad * 16;

        int4   c = __ldg(cp);          // feed q=0 (1 wf across warp)
        float4 v = __ldg(vp);

        #pragma unroll
        for (int q = 0; q < QCNT; ++q) {
            // 4 independent gathers for this q (the cap-bound stream)
            uint4 h0 = __ldg((const uint4*)(xb + ((size_t)(unsigned)c.x << 6)));
            uint4 h1 = __ldg((const uint4*)(xb + ((size_t)(unsigned)c.y << 6)));
            uint4 h2 = __ldg((const uint4*)(xb + ((size_t)(unsigned)c.z << 6)));
            uint4 h3 = __ldg((const uint4*)(xb + ((size_t)(unsigned)c.w << 6)));
            float4 vc = v;

            // prefetch feed for q+1 while the gathers are in flight
            if (q + 1 < QCNT) {
                c = __ldg(cp + (q + 1) * 8);
                v = __ldg(vp + (q + 1) * 8);
            }

            {
                float2 f0 = __half22float2(*(const __half2*)&h0.x);
                float2 f1 = __half22float2(*(const __half2*)&h0.y);
                float2 f2 = __half22float2(*(const __half2*)&h0.z);
                float2 f3 = __half22float2(*(const __half2*)&h0.w);
                acc[0] = fmaf(vc.x, f0.x, acc[0]); acc[1] = fmaf(vc.x, f0.y, acc[1]);
                acc[2] = fmaf(vc.x, f1.x, acc[2]); acc[3] = fmaf(vc.x, f1.y, acc[3]);
                acc[4] = fmaf(vc.x, f2.x, acc[4]); acc[5] = fmaf(vc.x, f2.y, acc[5]);
                acc[6] = fmaf(vc.x, f3.x, acc[6]); acc[7] = fmaf(vc.x, f3.y, acc[7]);
            }
            {
                float2 f0 = __half22float2(*(const __half2*)&h1.x);
                float2 f1 = __half22float2(*(const __half2*)&h1.y);
                float2 f2 = __half22float2(*(const __half2*)&h1.z);
                float2 f3 = __half22float2(*(const __half2*)&h1.w);
                acc[0] = fmaf(vc.y, f0.x, acc[0]); acc[1] = fmaf(vc.y, f0.y, acc[1]);
                acc[2] = fmaf(vc.y, f1.x, acc[2]); acc[3] = fmaf(vc.y, f1.y, acc[3]);
                acc[4] = fmaf(vc.y, f2.x, acc[4]); acc[5] = fmaf(vc.y, f2.y, acc[5]);
                acc[6] = fmaf(vc.y, f3.x, acc[6]); acc[7] = fmaf(vc.y, f3.y, acc[7]);
            }
            {
                float2 f0 = __half22float2(*(const __half2*)&h2.x);
                float2 f1 = __half22float2(*(const __half2*)&h2.y);
                float2 f2 = __half22float2(*(const __half2*)&h2.z);
                float2 f3 = __half22float2(*(const __half2*)&h2.w);
                acc[0] = fmaf(vc.z, f0.x, acc[0]); acc[1] = fmaf(vc.z, f0.y, acc[1]);
                acc[2] = fmaf(vc.z, f1.x, acc[2]); acc[3] = fmaf(vc.z, f1.y, acc[3]);
                acc[4] = fmaf(vc.z, f2.x, acc[4]); acc[5] = fmaf(vc.z, f2.y, acc[5]);
                acc[6] = fmaf(vc.z, f3.x, acc[6]); acc[7] = fmaf(vc.z, f3.y, acc[7]);
            }
            {
                float2 f0 = __half22float2(*(const __half2*)&h3.x);
                float2 f1 = __half22float2(*(const __half2*)&h3.y);
                float2 f2 = __half22float2(*(const __half2*)&h3.z);
                float2 f3 = __half22float2(*(const __half2*)&h3.w);
                acc[0] = fmaf(vc.w, f0.x, acc[0]); acc[1] = fmaf(vc.w, f0.y, acc[1]);
                acc[2] = fmaf(vc.w, f1.x, acc[2]); acc[3] = fmaf(vc.w, f1.y, acc[3]);
                acc[4] = fmaf(vc.w, f2.x, acc[4]); acc[5] = fmaf(vc.w, f2.y, acc[5]);
                acc[6] = fmaf(vc.w, f3.x, acc[6]); acc[7] = fmaf(vc.w, f3.y, acc[7]);
            }
        }
    }

    // Butterfly-reduce over the 8 groups (lane bits [2:4]).
    #pragma unroll
    for (int s = 4; s < 32; s <<= 1) {
        #pragma unroll
        for (int j = 0; j < 8; ++j)
            acc[j] += __shfl_xor_sync(0xffffffffu, acc[j], s);
    }

    // Lanes 0..3 hold final sums for b = quad*8 + j.
    if (lane < 4) {
        #pragma unroll
        for (int j = 0; j < 8; ++j)
            s_acc[w][lane * 8 + j] = acc[j];
    }
    __syncthreads();

    // Sector-coalesced store: thread t -> b = t/8, j = t%8 (8 consecutive n).
    const int b  = threadIdx.x >> 3;
    const int j  = threadIdx.x & 7;
    const int nn = blockIdx.x * WARPS_PER_BLOCK + j;
    if (nn < NDIM)
        out[(size_t)b * NDIM + nn] = s_acc[j][b];
}

// ---------------------------------------------------------------------------
// kernel_launch: inputs per metadata order: x_affine (f32), vals (f32), cols (i32)
// ---------------------------------------------------------------------------
extern "C" void kernel_launch(void* const* d_in, const int* in_sizes, int n_in,
                              void* d_out, int out_size)
{
    const float* x    = (const float*)d_in[0];
    const float* vals = (const float*)d_in[1];
    const int*   cols = (const int*)  d_in[2];
    float*       out  = (float*)d_out;

    (void)in_sizes; (void)n_in; (void)out_size;

    {
        int grid = (NDIM + 63) / 64;   // 513 blocks, 256 threads
        transpose_kernel<<<grid, 256>>>(x);
    }
    {
        gather_dot_kernel<<<NBLK, WARPS_PER_BLOCK * 32>>>(vals, cols, out);
    }
}

// round 14
// speedup vs baseline: 3.9852x; 1.0258x over previous
#include <cuda_runtime.h>
#include <cuda_fp16.h>
#include <cstdint>

// Problem constants (C=32,H=32,W=32,KS=3, B=32)
constexpr int NDIM = 32 * 32 * 32 + 1;   // 32769
constexpr int KDIM = 32 * 3 * 3;         // 288
constexpr int BDIM = 32;

constexpr int WARPS_PER_BLOCK = 8;
constexpr int NBLK = (NDIM + WARPS_PER_BLOCK - 1) / WARPS_PER_BLOCK;  // 4097
constexpr int QCNT = KDIM / 32;                                        // 9

// x transposed to [N, B] in fp16: 64 B rows; one LDG.128 with 4-lane groups
// gathers EIGHT different rows per instruction.
__device__ __align__(16) __half g_xT[(size_t)NDIM * BDIM];

// L2-only loads (bypass L1) for the single-use feed streams: keeps L1
// exclusively populated by x_T gather lines.
__device__ __forceinline__ int4 ldcg_int4(const int4* p)
{
    int4 r;
    asm volatile("ld.global.cg.v4.s32 {%0,%1,%2,%3}, [%4];"
                 : "=r"(r.x), "=r"(r.y), "=r"(r.z), "=r"(r.w) : "l"(p));
    return r;
}
__device__ __forceinline__ float4 ldcg_float4(const float4* p)
{
    float4 r;
    asm volatile("ld.global.cg.v4.f32 {%0,%1,%2,%3}, [%4];"
                 : "=f"(r.x), "=f"(r.y), "=f"(r.z), "=f"(r.w) : "l"(p));
    return r;
}

// ---------------------------------------------------------------------------
// Kernel 1: transpose + fp16-convert x [B, N] -> x_T [N, B].
// (R13 version: coalesced scalar loads, smem staging, uint4 stores.)
// ---------------------------------------------------------------------------
constexpr int TP_STRIDE = 40;   // halves per smem row (80 B, 16B-aligned)

__global__ __launch_bounds__(256) void transpose_kernel(const float* __restrict__ x)
{
    __shared__ __half tile[64][TP_STRIDE];

    const int n0 = blockIdx.x * 64;
    const int t  = threadIdx.x;

    #pragma unroll
    for (int i = 0; i < 8; ++i) {
        const int idx = i * 256 + t;
        const int b   = idx >> 6;
        const int nl  = idx & 63;
        const int n   = n0 + nl;
        if (n < NDIM)
            tile[nl][b] = __float2half(x[(size_t)b * NDIM + n]);
    }
    __syncthreads();

    const int nl   = t >> 2;
    const int quad = t & 3;
    const int n    = n0 + nl;
    if (n < NDIM) {
        uint4 u = *(const uint4*)&tile[nl][quad * 8];
        *(uint4*)((char*)g_xT + (size_t)n * 64 + quad * 16) = u;
    }
}

// ---------------------------------------------------------------------------
// Kernel 2: one warp per output row n, 4097 blocks (R12/R13 best shape).
//   g = lane>>2 : k within a 32-k chunk; quad = lane&3 : 16B slice of row.
// Feed: one int4 + one float4 per group per q via ld.global.cg (L2-only).
// Gather: 4 LDG.128 (__ldg, L1-cached) per group per q, 8 fp16 rows each.
// ---------------------------------------------------------------------------
__global__ __launch_bounds__(WARPS_PER_BLOCK * 32, 4)
void gather_dot_kernel(const float* __restrict__ vals,
                       const int*   __restrict__ cols,
                       float*       __restrict__ out)
{
    __shared__ float s_acc[WARPS_PER_BLOCK][33];   // [n_off][b], padded

    const int w    = threadIdx.x >> 5;
    const int lane = threadIdx.x & 31;
    const int g    = lane >> 2;   // group 0..7
    const int quad = lane & 3;    // 16B slice -> b = quad*8 .. quad*8+7
    const int n    = blockIdx.x * WARPS_PER_BLOCK + w;

    float acc[8] = {0.f, 0.f, 0.f, 0.f, 0.f, 0.f, 0.f, 0.f};

    if (n < NDIM) {
        const int4*   cp = (const int4*)  (cols + (size_t)n * KDIM) + g;
        const float4* vp = (const float4*)(vals + (size_t)n * KDIM) + g;
        const char*   xb = (const char*)g_xT + quad * 16;

        int4   c = ldcg_int4(cp);          // feed q=0 (L2-only)
        float4 v = ldcg_float4(vp);

        #pragma unroll
        for (int q = 0; q < QCNT; ++q) {
            // 4 independent gathers for this q (the cap-bound stream)
            uint4 h0 = __ldg((const uint4*)(xb + ((size_t)(unsigned)c.x << 6)));
            uint4 h1 = __ldg((const uint4*)(xb + ((size_t)(unsigned)c.y << 6)));
            uint4 h2 = __ldg((const uint4*)(xb + ((size_t)(unsigned)c.z << 6)));
            uint4 h3 = __ldg((const uint4*)(xb + ((size_t)(unsigned)c.w << 6)));
            float4 vc = v;

            // prefetch feed for q+1 while the gathers are in flight
            if (q + 1 < QCNT) {
                c = ldcg_int4(cp + (q + 1) * 8);
                v = ldcg_float4(vp + (q + 1) * 8);
            }

            {
                float2 f0 = __half22float2(*(const __half2*)&h0.x);
                float2 f1 = __half22float2(*(const __half2*)&h0.y);
                float2 f2 = __half22float2(*(const __half2*)&h0.z);
                float2 f3 = __half22float2(*(const __half2*)&h0.w);
                acc[0] = fmaf(vc.x, f0.x, acc[0]); acc[1] = fmaf(vc.x, f0.y, acc[1]);
                acc[2] = fmaf(vc.x, f1.x, acc[2]); acc[3] = fmaf(vc.x, f1.y, acc[3]);
                acc[4] = fmaf(vc.x, f2.x, acc[4]); acc[5] = fmaf(vc.x, f2.y, acc[5]);
                acc[6] = fmaf(vc.x, f3.x, acc[6]); acc[7] = fmaf(vc.x, f3.y, acc[7]);
            }
            {
                float2 f0 = __half22float2(*(const __half2*)&h1.x);
                float2 f1 = __half22float2(*(const __half2*)&h1.y);
                float2 f2 = __half22float2(*(const __half2*)&h1.z);
                float2 f3 = __half22float2(*(const __half2*)&h1.w);
                acc[0] = fmaf(vc.y, f0.x, acc[0]); acc[1] = fmaf(vc.y, f0.y, acc[1]);
                acc[2] = fmaf(vc.y, f1.x, acc[2]); acc[3] = fmaf(vc.y, f1.y, acc[3]);
                acc[4] = fmaf(vc.y, f2.x, acc[4]); acc[5] = fmaf(vc.y, f2.y, acc[5]);
                acc[6] = fmaf(vc.y, f3.x, acc[6]); acc[7] = fmaf(vc.y, f3.y, acc[7]);
            }
            {
                float2 f0 = __half22float2(*(const __half2*)&h2.x);
                float2 f1 = __half22float2(*(const __half2*)&h2.y);
                float2 f2 = __half22float2(*(const __half2*)&h2.z);
                float2 f3 = __half22float2(*(const __half2*)&h2.w);
                acc[0] = fmaf(vc.z, f0.x, acc[0]); acc[1] = fmaf(vc.z, f0.y, acc[1]);
                acc[2] = fmaf(vc.z, f1.x, acc[2]); acc[3] = fmaf(vc.z, f1.y, acc[3]);
                acc[4] = fmaf(vc.z, f2.x, acc[4]); acc[5] = fmaf(vc.z, f2.y, acc[5]);
                acc[6] = fmaf(vc.z, f3.x, acc[6]); acc[7] = fmaf(vc.z, f3.y, acc[7]);
            }
            {
                float2 f0 = __half22float2(*(const __half2*)&h3.x);
                float2 f1 = __half22float2(*(const __half2*)&h3.y);
                float2 f2 = __half22float2(*(const __half2*)&h3.z);
                float2 f3 = __half22float2(*(const __half2*)&h3.w);
                acc[0] = fmaf(vc.w, f0.x, acc[0]); acc[1] = fmaf(vc.w, f0.y, acc[1]);
                acc[2] = fmaf(vc.w, f1.x, acc[2]); acc[3] = fmaf(vc.w, f1.y, acc[3]);
                acc[4] = fmaf(vc.w, f2.x, acc[4]); acc[5] = fmaf(vc.w, f2.y, acc[5]);
                acc[6] = fmaf(vc.w, f3.x, acc[6]); acc[7] = fmaf(vc.w, f3.y, acc[7]);
            }
        }
    }

    // Butterfly-reduce over the 8 groups (lane bits [2:4]).
    #pragma unroll
    for (int s = 4; s < 32; s <<= 1) {
        #pragma unroll
        for (int j = 0; j < 8; ++j)
            acc[j] += __shfl_xor_sync(0xffffffffu, acc[j], s);
    }

    // Lanes 0..3 hold final sums for b = quad*8 + j.
    if (lane < 4) {
        #pragma unroll
        for (int j = 0; j < 8; ++j)
            s_acc[w][lane * 8 + j] = acc[j];
    }
    __syncthreads();

    // Sector-coalesced store: thread t -> b = t/8, j = t%8 (8 consecutive n).
    const int b  = threadIdx.x >> 3;
    const int j  = threadIdx.x & 7;
    const int nn = blockIdx.x * WARPS_PER_BLOCK + j;
    if (nn < NDIM)
        out[(size_t)b * NDIM + nn] = s_acc[j][b];
}

// ---------------------------------------------------------------------------
// kernel_launch: inputs per metadata order: x_affine (f32), vals (f32), cols (i32)
// ---------------------------------------------------------------------------
extern "C" void kernel_launch(void* const* d_in, const int* in_sizes, int n_in,
                              void* d_out, int out_size)
{
    const float* x    = (const float*)d_in[0];
    const float* vals = (const float*)d_in[1];
    const int*   cols = (const int*)  d_in[2];
    float*       out  = (float*)d_out;

    (void)in_sizes; (void)n_in; (void)out_size;

    {
        int grid = (NDIM + 63) / 64;   // 513 blocks, 256 threads
        transpose_kernel<<<grid, 256>>>(x);
    }
    {
        gather_dot_kernel<<<NBLK, WARPS_PER_BLOCK * 32>>>(vals, cols, out);
    }
}